// round 2
// baseline (speedup 1.0000x reference)
#include <cuda_runtime.h>
#include <math.h>

// ---------------- problem constants ----------------
#define BSZ   4
#define GHW   128            // grid_h == grid_w == 128
#define WS    16
#define TT    256            // tokens per window (16*16)
#define NWIN  256            // BSZ * 8 * 8 windows
#define NH    16
#define HD    64
#define CD    1024
#define C3    3072
#define MTOT  65536          // NWIN * TT
#define QSCALE 0.125f        // 1/sqrt(64)

// ---------------- scratch (no allocation allowed) ----------------
__device__ float g_Q[(size_t)NWIN * NH * TT * HD];   // 256 MB
__device__ float g_K[(size_t)NWIN * NH * TT * HD];   // 256 MB
__device__ float g_V[(size_t)NWIN * NH * TT * HD];   // 256 MB
__device__ float g_O[(size_t)MTOT * CD];             // 256 MB
__device__ float g_cos[TT * 32];
__device__ float g_sin[TT * 32];
__device__ int   g_xrow[MTOT];                       // window-order m -> grid-order token row

// m = win*256 + t ; win = b*64 + wh*8 + ww ; t = r*16 + c
__device__ __forceinline__ int xrow_of_m(int m) {
    int win = m >> 8, t = m & 255;
    int b = win >> 6, wh = (win >> 3) & 7, ww = win & 7;
    int r = t >> 4, c = t & 15;
    return b * (GHW * GHW) + (wh * WS + r) * GHW + (ww * WS + c);
}

// ---------------- init: rope table + gather map ----------------
__global__ void init_tables_kernel() {
    int i = blockIdx.x * 256 + threadIdx.x;       // grid covers MTOT
    if (i < MTOT) g_xrow[i] = xrow_of_m(i);
    if (i < TT * 32) {
        int t = i >> 5, j = i & 31;
        int r = t >> 4, c = t & 15;
        float inv = powf(10000.0f, -(float)j / 32.0f);
        float pos = (j < 16) ? (float)r : (float)c;
        float ang = pos * inv;
        g_cos[i] = cosf(ang);
        g_sin[i] = sinf(ang);
    }
}

// ---------------- QKV GEMM + RoPE + scatter ----------------
// C[m][f] = sum_k X[xrow(m)][k] * Wqkv[f][k]
// BM=BN=128, BK=32, 256 threads, 8x8 per thread (split 4+4 halves)
__global__ void __launch_bounds__(256) qkv_kernel(const float* __restrict__ x,
                                                  const float* __restrict__ Wqkv) {
    __shared__ float As[32][129];  // [k][row]  (odd stride: conflict-free stores)
    __shared__ float Bs[32][129];

    const int tid = threadIdx.x;
    const int lk  = tid & 31;      // k within tile (lane)
    const int lr  = tid >> 5;      // base row (warp id)
    const int ty4 = (tid >> 4) << 2;
    const int tx4 = (tid & 15) << 2;

    const int m0 = blockIdx.y * 128;
    const int n0 = blockIdx.x * 128;

    // precompute global offsets for the 16 A rows / 16 B rows this thread loads
    int aoff[16], boff[16];
#pragma unroll
    for (int p = 0; p < 16; ++p) {
        aoff[p] = g_xrow[m0 + lr + p * 8] * CD + lk;
        boff[p] = (n0 + lr + p * 8) * CD + lk;
    }

    float acc[8][8];
#pragma unroll
    for (int i = 0; i < 8; ++i)
#pragma unroll
        for (int j = 0; j < 8; ++j) acc[i][j] = 0.0f;

    for (int k0 = 0; k0 < CD; k0 += 32) {
#pragma unroll
        for (int p = 0; p < 16; ++p) As[lk][lr + p * 8] = x[aoff[p] + k0];
#pragma unroll
        for (int p = 0; p < 16; ++p) Bs[lk][lr + p * 8] = Wqkv[boff[p] + k0];
        __syncthreads();

#pragma unroll
        for (int kk = 0; kk < 32; ++kk) {
            float a[8], b[8];
#pragma unroll
            for (int i = 0; i < 4; ++i) {
                a[i]     = As[kk][ty4 + i];
                a[i + 4] = As[kk][64 + ty4 + i];
                b[i]     = Bs[kk][tx4 + i];
                b[i + 4] = Bs[kk][64 + tx4 + i];
            }
#pragma unroll
            for (int i = 0; i < 8; ++i)
#pragma unroll
                for (int j = 0; j < 8; ++j) acc[i][j] += a[i] * b[j];
        }
        __syncthreads();
    }

    // epilogue: RoPE (for s<2) + scale (s==0) + scatter to g_Q/g_K/g_V
#pragma unroll
    for (int ih = 0; ih < 2; ++ih) {
#pragma unroll
        for (int i = 0; i < 4; ++i) {
            const int m   = m0 + ih * 64 + ty4 + i;
            const int t   = m & 255;
            const int win = m >> 8;
#pragma unroll
            for (int jh = 0; jh < 2; ++jh) {
                const int f   = n0 + jh * 64 + tx4;       // 4-aligned column base
                const int s   = f >> 10;
                const int rem = f & 1023;
                const int h   = rem >> 6;
                const int d   = rem & 63;                 // == tx4 within head
                float v0 = acc[ih * 4 + i][jh * 4 + 0];
                float v1 = acc[ih * 4 + i][jh * 4 + 1];
                float v2 = acc[ih * 4 + i][jh * 4 + 2];
                float v3 = acc[ih * 4 + i][jh * 4 + 3];

                float* dst = (s == 0) ? g_Q : (s == 1) ? g_K : g_V;
                const size_t base = (((size_t)(win * NH + h)) * TT + t) * HD + d;

                float4 outv;
                if (s < 2) {
                    const int p0 = d >> 1;               // pair index (even)
                    float c0 = g_cos[t * 32 + p0],     s0 = g_sin[t * 32 + p0];
                    float c1 = g_cos[t * 32 + p0 + 1], s1 = g_sin[t * 32 + p0 + 1];
                    float o0 = v0 * c0 - v1 * s0;
                    float o1 = v0 * s0 + v1 * c0;
                    float o2 = v2 * c1 - v3 * s1;
                    float o3 = v2 * s1 + v3 * c1;
                    if (s == 0) { o0 *= QSCALE; o1 *= QSCALE; o2 *= QSCALE; o3 *= QSCALE; }
                    outv = make_float4(o0, o1, o2, o3);
                } else {
                    outv = make_float4(v0, v1, v2, v3);
                }
                *reinterpret_cast<float4*>(dst + base) = outv;
            }
        }
    }
}

// ---------------- attention: one block per (win, head) ----------------
__global__ void __launch_bounds__(256) attn_kernel() {
    extern __shared__ float sm[];
    float* sK = sm;
    float* sV = sm + TT * HD;

    const int bx  = blockIdx.x;                    // win*16 + h
    const int tid = threadIdx.x;                   // query index t
    const size_t base = (size_t)bx * TT * HD;

    for (int idx = tid; idx < TT * HD; idx += 256) {
        sK[idx] = g_K[base + idx];
        sV[idx] = g_V[base + idx];
    }

    float q[HD];
    {
        const float4* qp = reinterpret_cast<const float4*>(g_Q + base + (size_t)tid * HD);
#pragma unroll
        for (int d4 = 0; d4 < 16; ++d4) {
            float4 v = qp[d4];
            q[4 * d4 + 0] = v.x; q[4 * d4 + 1] = v.y;
            q[4 * d4 + 2] = v.z; q[4 * d4 + 3] = v.w;
        }
    }
    __syncthreads();

    float mrun = -1e30f, l = 0.0f;
    float acc[HD];
#pragma unroll
    for (int d = 0; d < HD; ++d) acc[d] = 0.0f;

    for (int j = 0; j < TT; ++j) {
        const float4* k4 = reinterpret_cast<const float4*>(sK + j * HD);
        float s = 0.0f;
#pragma unroll
        for (int d4 = 0; d4 < 16; ++d4) {
            float4 kv = k4[d4];
            s += q[4 * d4 + 0] * kv.x + q[4 * d4 + 1] * kv.y
               + q[4 * d4 + 2] * kv.z + q[4 * d4 + 3] * kv.w;
        }
        const float4* v4 = reinterpret_cast<const float4*>(sV + j * HD);
        if (s <= mrun) {
            float p = __expf(s - mrun);
            l += p;
#pragma unroll
            for (int d4 = 0; d4 < 16; ++d4) {
                float4 vv = v4[d4];
                acc[4 * d4 + 0] += p * vv.x; acc[4 * d4 + 1] += p * vv.y;
                acc[4 * d4 + 2] += p * vv.z; acc[4 * d4 + 3] += p * vv.w;
            }
        } else {
            float corr = __expf(mrun - s);   // exp(-inf)=0 on first iter
            mrun = s;
            l = l * corr + 1.0f;
#pragma unroll
            for (int d4 = 0; d4 < 16; ++d4) {
                float4 vv = v4[d4];
                acc[4 * d4 + 0] = acc[4 * d4 + 0] * corr + vv.x;
                acc[4 * d4 + 1] = acc[4 * d4 + 1] * corr + vv.y;
                acc[4 * d4 + 2] = acc[4 * d4 + 2] * corr + vv.z;
                acc[4 * d4 + 3] = acc[4 * d4 + 3] * corr + vv.w;
            }
        }
    }

    const float inv = 1.0f / l;
    const int win = bx >> 4, h = bx & 15;
    float4* op = reinterpret_cast<float4*>(g_O + ((size_t)(win * TT + tid)) * CD + h * HD);
#pragma unroll
    for (int d4 = 0; d4 < 16; ++d4)
        op[d4] = make_float4(acc[4 * d4 + 0] * inv, acc[4 * d4 + 1] * inv,
                             acc[4 * d4 + 2] * inv, acc[4 * d4 + 3] * inv);
}

// ---------------- proj GEMM + scatter back to grid layout ----------------
__global__ void __launch_bounds__(256) proj_kernel(const float* __restrict__ Wproj,
                                                   float* __restrict__ out) {
    __shared__ float As[32][129];
    __shared__ float Bs[32][129];

    const int tid = threadIdx.x;
    const int lk  = tid & 31;
    const int lr  = tid >> 5;
    const int ty4 = (tid >> 4) << 2;
    const int tx4 = (tid & 15) << 2;

    const int m0 = blockIdx.y * 128;
    const int n0 = blockIdx.x * 128;

    int boff[16];
#pragma unroll
    for (int p = 0; p < 16; ++p) boff[p] = (n0 + lr + p * 8) * CD + lk;

    float acc[8][8];
#pragma unroll
    for (int i = 0; i < 8; ++i)
#pragma unroll
        for (int j = 0; j < 8; ++j) acc[i][j] = 0.0f;

    for (int k0 = 0; k0 < CD; k0 += 32) {
#pragma unroll
        for (int p = 0; p < 16; ++p)
            As[lk][lr + p * 8] = g_O[(size_t)(m0 + lr + p * 8) * CD + k0 + lk];
#pragma unroll
        for (int p = 0; p < 16; ++p) Bs[lk][lr + p * 8] = Wproj[boff[p] + k0];
        __syncthreads();

#pragma unroll
        for (int kk = 0; kk < 32; ++kk) {
            float a[8], b[8];
#pragma unroll
            for (int i = 0; i < 4; ++i) {
                a[i]     = As[kk][ty4 + i];
                a[i + 4] = As[kk][64 + ty4 + i];
                b[i]     = Bs[kk][tx4 + i];
                b[i + 4] = Bs[kk][64 + tx4 + i];
            }
#pragma unroll
            for (int i = 0; i < 8; ++i)
#pragma unroll
                for (int j = 0; j < 8; ++j) acc[i][j] += a[i] * b[j];
        }
        __syncthreads();
    }

#pragma unroll
    for (int ih = 0; ih < 2; ++ih) {
#pragma unroll
        for (int i = 0; i < 4; ++i) {
            const int m    = m0 + ih * 64 + ty4 + i;
            const int orow = g_xrow[m];
#pragma unroll
            for (int jh = 0; jh < 2; ++jh) {
                const int f = n0 + jh * 64 + tx4;
                *reinterpret_cast<float4*>(out + (size_t)orow * CD + f) =
                    make_float4(acc[ih * 4 + i][jh * 4 + 0], acc[ih * 4 + i][jh * 4 + 1],
                                acc[ih * 4 + i][jh * 4 + 2], acc[ih * 4 + i][jh * 4 + 3]);
            }
        }
    }
}

// ---------------- launch ----------------
extern "C" void kernel_launch(void* const* d_in, const int* in_sizes, int n_in,
                              void* d_out, int out_size) {
    const float* x     = (const float*)d_in[0];
    // d_in[1] = position_ids (int64) — unused: window-local RoPE positions are fixed
    const float* Wqkv  = (const float*)d_in[2];
    const float* Wproj = (const float*)d_in[3];
    float* out = (float*)d_out;

    const int attn_smem = 2 * TT * HD * (int)sizeof(float);   // 128 KB
    cudaFuncSetAttribute(attn_kernel, cudaFuncAttributeMaxDynamicSharedMemorySize, attn_smem);

    init_tables_kernel<<<MTOT / 256, 256>>>();

    dim3 g1(C3 / 128, MTOT / 128);      // 24 x 512
    qkv_kernel<<<g1, 256>>>(x, Wqkv);

    attn_kernel<<<NWIN * NH, 256, attn_smem>>>();

    dim3 g3(CD / 128, MTOT / 128);      // 8 x 512
    proj_kernel<<<g3, 256>>>(Wproj, out);
}

// round 6
// speedup vs baseline: 1.7119x; 1.7119x over previous
#include <cuda_runtime.h>
#include <cuda_bf16.h>
#include <math.h>
#include <stdint.h>

// ---------------- problem constants ----------------
#define BSZ   4
#define GHW   128
#define WS    16
#define TT    256            // tokens per window
#define NWIN  256
#define NH    16
#define HD    64
#define CD    1024
#define C3    3072
#define MTOT  65536          // NWIN * TT
#define QSCALE 0.125f

// GEMM tile config (HMMA, static smem <= 48KB)
#define BM 128
#define BN 128
#define BK 32
#define KP 40                // padded row elems (20 words) -> conflict-free frag LDS
#define KPW 20               // words per row
// element offsets inside the static shared tile
#define AH_E 0
#define AL_E (128 * KP)
#define BH_E (2 * 128 * KP)
#define BL_E (3 * 128 * KP)

// ---------------- scratch (no allocation allowed) ----------------
__device__ float g_Q[(size_t)NWIN * NH * TT * HD];
__device__ float g_K[(size_t)NWIN * NH * TT * HD];
__device__ float g_V[(size_t)NWIN * NH * TT * HD];
__device__ __nv_bfloat16 g_xh[(size_t)MTOT * CD];
__device__ __nv_bfloat16 g_xl[(size_t)MTOT * CD];
__device__ __nv_bfloat16 g_oh[(size_t)MTOT * CD];
__device__ __nv_bfloat16 g_ol[(size_t)MTOT * CD];
__device__ __nv_bfloat16 g_wqh[(size_t)C3 * CD];
__device__ __nv_bfloat16 g_wql[(size_t)C3 * CD];
__device__ __nv_bfloat16 g_wph[(size_t)CD * CD];
__device__ __nv_bfloat16 g_wpl[(size_t)CD * CD];
__device__ float g_cos[TT * 32];
__device__ float g_sin[TT * 32];
__device__ int   g_xrow[MTOT];

__device__ __forceinline__ int xrow_of_m(int m) {
    int win = m >> 8, t = m & 255;
    int b = win >> 6, wh = (win >> 3) & 7, ww = win & 7;
    int r = t >> 4, c = t & 15;
    return b * (GHW * GHW) + (wh * WS + r) * GHW + (ww * WS + c);
}

__device__ __forceinline__ void mma_bf16(float* c, const uint32_t* a, uint32_t b0, uint32_t b1) {
    asm volatile("mma.sync.aligned.m16n8k16.row.col.f32.bf16.bf16.f32 "
                 "{%0,%1,%2,%3}, {%4,%5,%6,%7}, {%8,%9}, {%0,%1,%2,%3};"
                 : "+f"(c[0]), "+f"(c[1]), "+f"(c[2]), "+f"(c[3])
                 : "r"(a[0]), "r"(a[1]), "r"(a[2]), "r"(a[3]), "r"(b0), "r"(b1));
}

// ---------------- init: rope table + gather map ----------------
__global__ void init_tables_kernel() {
    int i = blockIdx.x * 256 + threadIdx.x;
    if (i < MTOT) g_xrow[i] = xrow_of_m(i);
    if (i < TT * 32) {
        int t = i >> 5, j = i & 31;
        int r = t >> 4, c = t & 15;
        float inv = powf(10000.0f, -(float)j / 32.0f);
        float pos = (j < 16) ? (float)r : (float)c;
        g_cos[i] = cosf(pos * inv);
        g_sin[i] = sinf(pos * inv);
    }
}

// ---------------- fp32 -> bf16 hi/lo split helpers ----------------
union U4BF8 { uint4 u; __nv_bfloat16 h[8]; };

__device__ __forceinline__ void split8(const float* v, U4BF8& hi, U4BF8& lo) {
#pragma unroll
    for (int j = 0; j < 8; ++j) {
        __nv_bfloat16 h = __float2bfloat16(v[j]);
        hi.h[j] = h;
        lo.h[j] = __float2bfloat16(v[j] - __bfloat162float(h));
    }
}

__global__ void __launch_bounds__(256) conv_x_kernel(const float* __restrict__ x) {
    int i = blockIdx.x * 256 + threadIdx.x;
    int e0 = i * 8;
    int m = e0 >> 10, k = e0 & 1023;
    int src = xrow_of_m(m);
    float v[8];
    const float4* sp = reinterpret_cast<const float4*>(x + (size_t)src * CD + k);
    float4 a = sp[0], b = sp[1];
    v[0]=a.x; v[1]=a.y; v[2]=a.z; v[3]=a.w; v[4]=b.x; v[5]=b.y; v[6]=b.z; v[7]=b.w;
    U4BF8 hi, lo; split8(v, hi, lo);
    reinterpret_cast<uint4*>(g_xh + (size_t)m * CD + k)[0] = hi.u;
    reinterpret_cast<uint4*>(g_xl + (size_t)m * CD + k)[0] = lo.u;
}

__global__ void __launch_bounds__(256) conv_w_kernel(const float* __restrict__ src, int which) {
    int i = blockIdx.x * 256 + threadIdx.x;
    int e0 = i * 8;
    float v[8];
    const float4* sp = reinterpret_cast<const float4*>(src + e0);
    float4 a = sp[0], b = sp[1];
    v[0]=a.x; v[1]=a.y; v[2]=a.z; v[3]=a.w; v[4]=b.x; v[5]=b.y; v[6]=b.z; v[7]=b.w;
    U4BF8 h4, l4; split8(v, h4, l4);
    __nv_bfloat16* hi = (which == 0) ? g_wqh : g_wph;
    __nv_bfloat16* lo = (which == 0) ? g_wql : g_wpl;
    reinterpret_cast<uint4*>(hi + e0)[0] = h4.u;
    reinterpret_cast<uint4*>(lo + e0)[0] = l4.u;
}

// ---------------- HMMA split-bf16 GEMM (static smem, no template) ----------------
// D[m][n] = sum_k A[m][k] * B[n][k], 3-term split accumulate.
// mode 0: A=g_xh/g_xl, B=g_wqh/g_wql -> RoPE+scale+scatter to Q/K/V
// mode 1: A=g_oh/g_ol, B=g_wph/g_wpl -> scatter rows via g_xrow to out
__global__ void __launch_bounds__(256) hmma_gemm_kernel(int mode, float* __restrict__ out) {
    __shared__ __nv_bfloat16 ts[4 * 128 * KP];   // 40960 bytes (<48KB, no opt-in)

    const __nv_bfloat16* Ahi = (mode == 0) ? g_xh : g_oh;
    const __nv_bfloat16* Alo = (mode == 0) ? g_xl : g_ol;
    const __nv_bfloat16* Bhi = (mode == 0) ? g_wqh : g_wph;
    const __nv_bfloat16* Blo = (mode == 0) ? g_wql : g_wpl;

    const int tid  = threadIdx.x;
    const int wid  = tid >> 5;
    const int lane = tid & 31;
    const int wm   = wid & 3;           // 4 warps in M (32 rows each)
    const int wn   = wid >> 2;          // 2 warps in N (64 cols each)
    const int grp  = lane >> 2;         // 0..7
    const int tig  = lane & 3;          // 0..3
    const int m0   = blockIdx.y * BM;
    const int n0   = blockIdx.x * BN;

    // staging map: u = tid*2 + j ; row = u>>2 (0..127), seg = (u&3)*8 (0..24)
    const int u0 = tid * 2, u1 = tid * 2 + 1;
    const int r0s = u0 >> 2, s0s = (u0 & 3) * 8;
    const int r1s = u1 >> 2, s1s = (u1 & 3) * 8;
    const size_t gA0 = (size_t)(m0 + r0s) * CD + s0s;
    const size_t gA1 = (size_t)(m0 + r1s) * CD + s1s;
    const size_t gB0 = (size_t)(n0 + r0s) * CD + s0s;
    const size_t gB1 = (size_t)(n0 + r1s) * CD + s1s;

    const uint32_t* s32 = reinterpret_cast<const uint32_t*>(ts);

    float C[2][8][4];
#pragma unroll
    for (int a = 0; a < 2; ++a)
#pragma unroll
        for (int n = 0; n < 8; ++n)
#pragma unroll
            for (int j = 0; j < 4; ++j) C[a][n][j] = 0.0f;

#pragma unroll 1
    for (int c = 0; c < CD / BK; ++c) {
        const int k0 = c * BK;
        uint4 v0 = *reinterpret_cast<const uint4*>(Ahi + gA0 + k0);
        uint4 v1 = *reinterpret_cast<const uint4*>(Ahi + gA1 + k0);
        uint4 v2 = *reinterpret_cast<const uint4*>(Alo + gA0 + k0);
        uint4 v3 = *reinterpret_cast<const uint4*>(Alo + gA1 + k0);
        uint4 v4 = *reinterpret_cast<const uint4*>(Bhi + gB0 + k0);
        uint4 v5 = *reinterpret_cast<const uint4*>(Bhi + gB1 + k0);
        uint4 v6 = *reinterpret_cast<const uint4*>(Blo + gB0 + k0);
        uint4 v7 = *reinterpret_cast<const uint4*>(Blo + gB1 + k0);

        __syncthreads();   // previous iteration's reads done
        *reinterpret_cast<uint4*>(ts + AH_E + r0s * KP + s0s) = v0;
        *reinterpret_cast<uint4*>(ts + AH_E + r1s * KP + s1s) = v1;
        *reinterpret_cast<uint4*>(ts + AL_E + r0s * KP + s0s) = v2;
        *reinterpret_cast<uint4*>(ts + AL_E + r1s * KP + s1s) = v3;
        *reinterpret_cast<uint4*>(ts + BH_E + r0s * KP + s0s) = v4;
        *reinterpret_cast<uint4*>(ts + BH_E + r1s * KP + s1s) = v5;
        *reinterpret_cast<uint4*>(ts + BL_E + r0s * KP + s0s) = v6;
        *reinterpret_cast<uint4*>(ts + BL_E + r1s * KP + s1s) = v7;
        __syncthreads();   // tile ready

#pragma unroll
        for (int ks = 0; ks < 2; ++ks) {
            const int kw = ks * 8 + tig;          // word offset of this lane's k-pair
            uint32_t ah[2][4], al[2][4];
#pragma unroll
            for (int a = 0; a < 2; ++a) {
                const int r = wm * 32 + a * 16 + grp;
                ah[a][0] = s32[(AH_E / 2) + (r    ) * KPW + kw    ];
                ah[a][1] = s32[(AH_E / 2) + (r + 8) * KPW + kw    ];
                ah[a][2] = s32[(AH_E / 2) + (r    ) * KPW + kw + 4];
                ah[a][3] = s32[(AH_E / 2) + (r + 8) * KPW + kw + 4];
                al[a][0] = s32[(AL_E / 2) + (r    ) * KPW + kw    ];
                al[a][1] = s32[(AL_E / 2) + (r + 8) * KPW + kw    ];
                al[a][2] = s32[(AL_E / 2) + (r    ) * KPW + kw + 4];
                al[a][3] = s32[(AL_E / 2) + (r + 8) * KPW + kw + 4];
            }
#pragma unroll
            for (int nt = 0; nt < 8; ++nt) {
                const int nr = wn * 64 + nt * 8 + grp;
                uint32_t bh0 = s32[(BH_E / 2) + nr * KPW + kw];
                uint32_t bh1 = s32[(BH_E / 2) + nr * KPW + kw + 4];
                uint32_t bl0 = s32[(BL_E / 2) + nr * KPW + kw];
                uint32_t bl1 = s32[(BL_E / 2) + nr * KPW + kw + 4];
#pragma unroll
                for (int a = 0; a < 2; ++a) {
                    mma_bf16(C[a][nt], ah[a], bh0, bh1);   // Ah*Bh
                    mma_bf16(C[a][nt], al[a], bh0, bh1);   // Al*Bh
                    mma_bf16(C[a][nt], ah[a], bl0, bl1);   // Ah*Bl
                }
            }
        }
    }

    // ---------------- epilogue ----------------
#pragma unroll
    for (int a = 0; a < 2; ++a) {
#pragma unroll
        for (int nt = 0; nt < 8; ++nt) {
            const int col = n0 + wn * 64 + nt * 8 + 2 * tig;
#pragma unroll
            for (int half = 0; half < 2; ++half) {
                const int row = m0 + wm * 32 + a * 16 + grp + half * 8;
                float v0 = C[a][nt][half * 2 + 0];
                float v1 = C[a][nt][half * 2 + 1];
                if (mode == 0) {
                    const int t = row & 255, win = row >> 8;
                    const int s = col >> 10;
                    const int h = (col & 1023) >> 6;
                    const int d = col & 63;                 // even
                    float o0, o1;
                    if (s < 2) {
                        const int p = d >> 1;
                        float cc = g_cos[t * 32 + p], ss = g_sin[t * 32 + p];
                        o0 = v0 * cc - v1 * ss;
                        o1 = v0 * ss + v1 * cc;
                        if (s == 0) { o0 *= QSCALE; o1 *= QSCALE; }
                    } else { o0 = v0; o1 = v1; }
                    float* dst = (s == 0) ? g_Q : (s == 1) ? g_K : g_V;
                    const size_t base = (((size_t)(win * NH + h)) * TT + t) * (size_t)HD + d;
                    *reinterpret_cast<float2*>(dst + base) = make_float2(o0, o1);
                } else {
                    const size_t orow = (size_t)g_xrow[row];
                    *reinterpret_cast<float2*>(out + orow * CD + col) = make_float2(v0, v1);
                }
            }
        }
    }
}

// ---------------- attention: one block per (win, head), writes bf16 hi/lo O ----------------
__global__ void __launch_bounds__(256) attn_kernel() {
    extern __shared__ float smf[];
    float* sK = smf;
    float* sV = smf + TT * HD;

    const int bx = blockIdx.x;                     // win*16 + h
    const int tid = threadIdx.x;                   // query index t
    const size_t base = (size_t)bx * TT * HD;

    for (int idx = tid; idx < TT * HD; idx += 256) {
        sK[idx] = g_K[base + idx];
        sV[idx] = g_V[base + idx];
    }

    float q[HD];
    {
        const float4* qp = reinterpret_cast<const float4*>(g_Q + base + (size_t)tid * HD);
#pragma unroll
        for (int d4 = 0; d4 < 16; ++d4) {
            float4 v = qp[d4];
            q[4*d4+0]=v.x; q[4*d4+1]=v.y; q[4*d4+2]=v.z; q[4*d4+3]=v.w;
        }
    }
    __syncthreads();

    float mrun = -1e30f, l = 0.0f;
    float acc[HD];
#pragma unroll
    for (int d = 0; d < HD; ++d) acc[d] = 0.0f;

    for (int j = 0; j < TT; ++j) {
        const float4* k4 = reinterpret_cast<const float4*>(sK + j * HD);
        float s = 0.0f;
#pragma unroll
        for (int d4 = 0; d4 < 16; ++d4) {
            float4 kv = k4[d4];
            s += q[4*d4+0]*kv.x + q[4*d4+1]*kv.y + q[4*d4+2]*kv.z + q[4*d4+3]*kv.w;
        }
        const float4* v4 = reinterpret_cast<const float4*>(sV + j * HD);
        if (s <= mrun) {
            float p = __expf(s - mrun);
            l += p;
#pragma unroll
            for (int d4 = 0; d4 < 16; ++d4) {
                float4 vv = v4[d4];
                acc[4*d4+0] += p*vv.x; acc[4*d4+1] += p*vv.y;
                acc[4*d4+2] += p*vv.z; acc[4*d4+3] += p*vv.w;
            }
        } else {
            float corr = __expf(mrun - s);
            mrun = s;
            l = l * corr + 1.0f;
#pragma unroll
            for (int d4 = 0; d4 < 16; ++d4) {
                float4 vv = v4[d4];
                acc[4*d4+0] = acc[4*d4+0]*corr + vv.x;
                acc[4*d4+1] = acc[4*d4+1]*corr + vv.y;
                acc[4*d4+2] = acc[4*d4+2]*corr + vv.z;
                acc[4*d4+3] = acc[4*d4+3]*corr + vv.w;
            }
        }
    }

    const float inv = 1.0f / l;
    const int win = bx >> 4, h = bx & 15;
    const size_t orow = (size_t)(win * TT + tid) * CD + h * HD;
#pragma unroll
    for (int d8 = 0; d8 < 8; ++d8) {
        float v[8];
#pragma unroll
        for (int j = 0; j < 8; ++j) v[j] = acc[d8 * 8 + j] * inv;
        U4BF8 hi, lo; split8(v, hi, lo);
        reinterpret_cast<uint4*>(g_oh + orow + d8 * 8)[0] = hi.u;
        reinterpret_cast<uint4*>(g_ol + orow + d8 * 8)[0] = lo.u;
    }
}

// ---------------- launch ----------------
extern "C" void kernel_launch(void* const* d_in, const int* in_sizes, int n_in,
                              void* d_out, int out_size) {
    const float* x     = (const float*)d_in[0];
    // d_in[1] = position_ids (unused: window-local RoPE positions are fixed)
    const float* Wqkv  = (const float*)d_in[2];
    const float* Wproj = (const float*)d_in[3];
    float* out = (float*)d_out;

    const int attn_smem = 2 * TT * HD * (int)sizeof(float);   // 128 KB (R1-proven mechanism)
    cudaFuncSetAttribute(attn_kernel, cudaFuncAttributeMaxDynamicSharedMemorySize, attn_smem);

    init_tables_kernel<<<MTOT / 256, 256>>>();
    conv_x_kernel<<<(MTOT * (CD / 8)) / 256, 256>>>(x);
    conv_w_kernel<<<(C3 * CD / 8) / 256, 256>>>(Wqkv, 0);
    conv_w_kernel<<<(CD * CD / 8) / 256, 256>>>(Wproj, 1);

    dim3 g1(C3 / BN, MTOT / BM);   // 24 x 512
    hmma_gemm_kernel<<<g1, 256>>>(0, nullptr);

    attn_kernel<<<NWIN * NH, 256, attn_smem>>>();

    dim3 g2(CD / BN, MTOT / BM);   // 8 x 512
    hmma_gemm_kernel<<<g2, 256>>>(1, out);
}

// round 7
// speedup vs baseline: 1.9561x; 1.1426x over previous
#include <cuda_runtime.h>
#include <cuda_bf16.h>
#include <math.h>
#include <stdint.h>

// ---------------- problem constants ----------------
#define BSZ   4
#define GHW   128
#define WS    16
#define TT    256            // tokens per window
#define NWIN  256
#define NH    16
#define HD    64
#define CD    1024
#define C3    3072
#define MTOT  65536          // NWIN * TT
#define QSCALE 0.125f

// GEMM tile config (HMMA, cp.async double-buffered)
#define BM 128
#define BN 128
#define BK 32
#define KP 40                // padded row elems (20 words) -> conflict-free frag LDS
#define KPW 20               // words per row
// element offsets inside one stage
#define AH_E 0
#define AL_E (128 * KP)
#define BH_E (2 * 128 * KP)
#define BL_E (3 * 128 * KP)
#define STAGE_E (4 * 128 * KP)            // 20480 elems
#define STAGE_B (STAGE_E * 2)             // 40960 bytes
#define STAGE_W (STAGE_E / 2)             // 10240 words
#define GEMM_SMEM (2 * STAGE_B)           // 81920 bytes dynamic

// ---------------- scratch (no allocation allowed) ----------------
__device__ float g_Q[(size_t)NWIN * NH * TT * HD];
__device__ float g_K[(size_t)NWIN * NH * TT * HD];
__device__ float g_V[(size_t)NWIN * NH * TT * HD];
__device__ __nv_bfloat16 g_xh[(size_t)MTOT * CD];
__device__ __nv_bfloat16 g_xl[(size_t)MTOT * CD];
__device__ __nv_bfloat16 g_oh[(size_t)MTOT * CD];
__device__ __nv_bfloat16 g_ol[(size_t)MTOT * CD];
__device__ __nv_bfloat16 g_wqh[(size_t)C3 * CD];
__device__ __nv_bfloat16 g_wql[(size_t)C3 * CD];
__device__ __nv_bfloat16 g_wph[(size_t)CD * CD];
__device__ __nv_bfloat16 g_wpl[(size_t)CD * CD];
__device__ float g_cos[TT * 32];
__device__ float g_sin[TT * 32];
__device__ int   g_xrow[MTOT];

__device__ __forceinline__ int xrow_of_m(int m) {
    int win = m >> 8, t = m & 255;
    int b = win >> 6, wh = (win >> 3) & 7, ww = win & 7;
    int r = t >> 4, c = t & 15;
    return b * (GHW * GHW) + (wh * WS + r) * GHW + (ww * WS + c);
}

__device__ __forceinline__ void mma_bf16(float* c, const uint32_t* a, uint32_t b0, uint32_t b1) {
    asm volatile("mma.sync.aligned.m16n8k16.row.col.f32.bf16.bf16.f32 "
                 "{%0,%1,%2,%3}, {%4,%5,%6,%7}, {%8,%9}, {%0,%1,%2,%3};"
                 : "+f"(c[0]), "+f"(c[1]), "+f"(c[2]), "+f"(c[3])
                 : "r"(a[0]), "r"(a[1]), "r"(a[2]), "r"(a[3]), "r"(b0), "r"(b1));
}

__device__ __forceinline__ uint32_t smem_u32(const void* p) {
    uint32_t a;
    asm("{ .reg .u64 t; cvta.to.shared.u64 t, %1; cvt.u32.u64 %0, t; }" : "=r"(a) : "l"(p));
    return a;
}

#define CP16(dst, src) \
    asm volatile("cp.async.cg.shared.global [%0], [%1], 16;" :: "r"(dst), "l"(src) : "memory")
#define CP_COMMIT() asm volatile("cp.async.commit_group;" ::: "memory")
#define CP_WAIT1()  asm volatile("cp.async.wait_group 1;" ::: "memory")
#define CP_WAIT0()  asm volatile("cp.async.wait_group 0;" ::: "memory")

// ---------------- init: rope table + gather map ----------------
__global__ void init_tables_kernel() {
    int i = blockIdx.x * 256 + threadIdx.x;
    if (i < MTOT) g_xrow[i] = xrow_of_m(i);
    if (i < TT * 32) {
        int t = i >> 5, j = i & 31;
        int r = t >> 4, c = t & 15;
        float inv = powf(10000.0f, -(float)j / 32.0f);
        float pos = (j < 16) ? (float)r : (float)c;
        g_cos[i] = cosf(pos * inv);
        g_sin[i] = sinf(pos * inv);
    }
}

// ---------------- fp32 -> bf16 hi/lo split helpers ----------------
union U4BF8 { uint4 u; __nv_bfloat16 h[8]; };

__device__ __forceinline__ void split8(const float* v, U4BF8& hi, U4BF8& lo) {
#pragma unroll
    for (int j = 0; j < 8; ++j) {
        __nv_bfloat16 h = __float2bfloat16(v[j]);
        hi.h[j] = h;
        lo.h[j] = __float2bfloat16(v[j] - __bfloat162float(h));
    }
}

__global__ void __launch_bounds__(256) conv_x_kernel(const float* __restrict__ x) {
    int i = blockIdx.x * 256 + threadIdx.x;
    int e0 = i * 8;
    int m = e0 >> 10, k = e0 & 1023;
    int src = xrow_of_m(m);
    float v[8];
    const float4* sp = reinterpret_cast<const float4*>(x + (size_t)src * CD + k);
    float4 a = sp[0], b = sp[1];
    v[0]=a.x; v[1]=a.y; v[2]=a.z; v[3]=a.w; v[4]=b.x; v[5]=b.y; v[6]=b.z; v[7]=b.w;
    U4BF8 hi, lo; split8(v, hi, lo);
    reinterpret_cast<uint4*>(g_xh + (size_t)m * CD + k)[0] = hi.u;
    reinterpret_cast<uint4*>(g_xl + (size_t)m * CD + k)[0] = lo.u;
}

__global__ void __launch_bounds__(256) conv_w_kernel(const float* __restrict__ src, int which) {
    int i = blockIdx.x * 256 + threadIdx.x;
    int e0 = i * 8;
    float v[8];
    const float4* sp = reinterpret_cast<const float4*>(src + e0);
    float4 a = sp[0], b = sp[1];
    v[0]=a.x; v[1]=a.y; v[2]=a.z; v[3]=a.w; v[4]=b.x; v[5]=b.y; v[6]=b.z; v[7]=b.w;
    U4BF8 h4, l4; split8(v, h4, l4);
    __nv_bfloat16* hi = (which == 0) ? g_wqh : g_wph;
    __nv_bfloat16* lo = (which == 0) ? g_wql : g_wpl;
    reinterpret_cast<uint4*>(hi + e0)[0] = h4.u;
    reinterpret_cast<uint4*>(lo + e0)[0] = l4.u;
}

// ---------------- HMMA split-bf16 GEMM (cp.async 2-stage pipeline) ----------------
// D[m][n] = sum_k A[m][k] * B[n][k], 3-term split accumulate.
// mode 0: A=g_xh/g_xl, B=g_wqh/g_wql -> RoPE+scale+scatter to Q/K/V
// mode 1: A=g_oh/g_ol, B=g_wph/g_wpl -> scatter rows via g_xrow to out
__global__ void __launch_bounds__(256) hmma_gemm_kernel(int mode, float* __restrict__ out) {
    extern __shared__ __nv_bfloat16 ts[];   // 2 stages x 40960 bytes

    const __nv_bfloat16* Ahi = (mode == 0) ? g_xh : g_oh;
    const __nv_bfloat16* Alo = (mode == 0) ? g_xl : g_ol;
    const __nv_bfloat16* Bhi = (mode == 0) ? g_wqh : g_wph;
    const __nv_bfloat16* Blo = (mode == 0) ? g_wql : g_wpl;

    const int tid  = threadIdx.x;
    const int wid  = tid >> 5;
    const int lane = tid & 31;
    const int wm   = wid & 3;           // 4 warps in M (32 rows each)
    const int wn   = wid >> 2;          // 2 warps in N (64 cols each)
    const int grp  = lane >> 2;         // 0..7
    const int tig  = lane & 3;          // 0..3
    const int m0   = blockIdx.y * BM;
    const int n0   = blockIdx.x * BN;

    // staging map (R6-proven): u = tid*2 + j ; row = u>>2, seg = (u&3)*8 elems (16B)
    const int u0 = tid * 2, u1 = tid * 2 + 1;
    const int r0s = u0 >> 2, s0s = (u0 & 3) * 8;
    const int r1s = u1 >> 2, s1s = (u1 & 3) * 8;
    const size_t gA0 = (size_t)(m0 + r0s) * CD + s0s;
    const size_t gA1 = (size_t)(m0 + r1s) * CD + s1s;
    const size_t gB0 = (size_t)(n0 + r0s) * CD + s0s;
    const size_t gB1 = (size_t)(n0 + r1s) * CD + s1s;

    const uint32_t ts_u32 = smem_u32(ts);
    // per-thread smem byte offsets inside a stage (fixed)
    const uint32_t dAH0 = (uint32_t)(AH_E + r0s * KP + s0s) * 2;
    const uint32_t dAH1 = (uint32_t)(AH_E + r1s * KP + s1s) * 2;
    const uint32_t dAL0 = (uint32_t)(AL_E + r0s * KP + s0s) * 2;
    const uint32_t dAL1 = (uint32_t)(AL_E + r1s * KP + s1s) * 2;
    const uint32_t dBH0 = (uint32_t)(BH_E + r0s * KP + s0s) * 2;
    const uint32_t dBH1 = (uint32_t)(BH_E + r1s * KP + s1s) * 2;
    const uint32_t dBL0 = (uint32_t)(BL_E + r0s * KP + s0s) * 2;
    const uint32_t dBL1 = (uint32_t)(BL_E + r1s * KP + s1s) * 2;

    const uint32_t* s32 = reinterpret_cast<const uint32_t*>(ts);

    float C[2][8][4];
#pragma unroll
    for (int a = 0; a < 2; ++a)
#pragma unroll
        for (int n = 0; n < 8; ++n)
#pragma unroll
            for (int j = 0; j < 4; ++j) C[a][n][j] = 0.0f;

    const int NCH = CD / BK;   // 32

    // prologue: stage 0 loads in flight
    {
        const uint32_t sb = ts_u32;
        CP16(sb + dAH0, Ahi + gA0); CP16(sb + dAH1, Ahi + gA1);
        CP16(sb + dAL0, Alo + gA0); CP16(sb + dAL1, Alo + gA1);
        CP16(sb + dBH0, Bhi + gB0); CP16(sb + dBH1, Bhi + gB1);
        CP16(sb + dBL0, Blo + gB0); CP16(sb + dBL1, Blo + gB1);
        CP_COMMIT();
    }

#pragma unroll 1
    for (int c = 0; c < NCH; ++c) {
        if (c + 1 < NCH) {
            const int k1 = (c + 1) * BK;
            const uint32_t sb = ts_u32 + (uint32_t)((c + 1) & 1) * STAGE_B;
            CP16(sb + dAH0, Ahi + gA0 + k1); CP16(sb + dAH1, Ahi + gA1 + k1);
            CP16(sb + dAL0, Alo + gA0 + k1); CP16(sb + dAL1, Alo + gA1 + k1);
            CP16(sb + dBH0, Bhi + gB0 + k1); CP16(sb + dBH1, Bhi + gB1 + k1);
            CP16(sb + dBL0, Blo + gB0 + k1); CP16(sb + dBL1, Blo + gB1 + k1);
            CP_COMMIT();
            CP_WAIT1();            // stage c's group retired
        } else {
            CP_WAIT0();
        }
        __syncthreads();           // stage c visible to all warps

        const uint32_t sw = (uint32_t)(c & 1) * STAGE_W;   // stage word base
#pragma unroll
        for (int ks = 0; ks < 2; ++ks) {
            const int kw = ks * 8 + tig;          // word offset of this lane's k-pair
            uint32_t ah[2][4], al[2][4];
#pragma unroll
            for (int a = 0; a < 2; ++a) {
                const int r = wm * 32 + a * 16 + grp;
                ah[a][0] = s32[sw + (AH_E / 2) + (r    ) * KPW + kw    ];
                ah[a][1] = s32[sw + (AH_E / 2) + (r + 8) * KPW + kw    ];
                ah[a][2] = s32[sw + (AH_E / 2) + (r    ) * KPW + kw + 4];
                ah[a][3] = s32[sw + (AH_E / 2) + (r + 8) * KPW + kw + 4];
                al[a][0] = s32[sw + (AL_E / 2) + (r    ) * KPW + kw    ];
                al[a][1] = s32[sw + (AL_E / 2) + (r + 8) * KPW + kw    ];
                al[a][2] = s32[sw + (AL_E / 2) + (r    ) * KPW + kw + 4];
                al[a][3] = s32[sw + (AL_E / 2) + (r + 8) * KPW + kw + 4];
            }
#pragma unroll
            for (int nt = 0; nt < 8; ++nt) {
                const int nr = wn * 64 + nt * 8 + grp;
                uint32_t bh0 = s32[sw + (BH_E / 2) + nr * KPW + kw];
                uint32_t bh1 = s32[sw + (BH_E / 2) + nr * KPW + kw + 4];
                uint32_t bl0 = s32[sw + (BL_E / 2) + nr * KPW + kw];
                uint32_t bl1 = s32[sw + (BL_E / 2) + nr * KPW + kw + 4];
#pragma unroll
                for (int a = 0; a < 2; ++a) {
                    mma_bf16(C[a][nt], ah[a], bh0, bh1);   // Ah*Bh
                    mma_bf16(C[a][nt], al[a], bh0, bh1);   // Al*Bh
                    mma_bf16(C[a][nt], ah[a], bl0, bl1);   // Ah*Bl
                }
            }
        }
        __syncthreads();           // all warps done reading stage c before overwrite
    }

    // ---------------- epilogue ----------------
#pragma unroll
    for (int a = 0; a < 2; ++a) {
#pragma unroll
        for (int nt = 0; nt < 8; ++nt) {
            const int col = n0 + wn * 64 + nt * 8 + 2 * tig;
#pragma unroll
            for (int half = 0; half < 2; ++half) {
                const int row = m0 + wm * 32 + a * 16 + grp + half * 8;
                float v0 = C[a][nt][half * 2 + 0];
                float v1 = C[a][nt][half * 2 + 1];
                if (mode == 0) {
                    const int t = row & 255, win = row >> 8;
                    const int s = col >> 10;
                    const int h = (col & 1023) >> 6;
                    const int d = col & 63;                 // even
                    float o0, o1;
                    if (s < 2) {
                        const int p = d >> 1;
                        float cc = g_cos[t * 32 + p], ss = g_sin[t * 32 + p];
                        o0 = v0 * cc - v1 * ss;
                        o1 = v0 * ss + v1 * cc;
                        if (s == 0) { o0 *= QSCALE; o1 *= QSCALE; }
                    } else { o0 = v0; o1 = v1; }
                    float* dst = (s == 0) ? g_Q : (s == 1) ? g_K : g_V;
                    const size_t base = (((size_t)(win * NH + h)) * TT + t) * (size_t)HD + d;
                    *reinterpret_cast<float2*>(dst + base) = make_float2(o0, o1);
                } else {
                    const size_t orow = (size_t)g_xrow[row];
                    *reinterpret_cast<float2*>(out + orow * CD + col) = make_float2(v0, v1);
                }
            }
        }
    }
}

// ---------------- attention: one block per (win, head), writes bf16 hi/lo O ----------------
__global__ void __launch_bounds__(256) attn_kernel() {
    extern __shared__ float smf[];
    float* sK = smf;
    float* sV = smf + TT * HD;

    const int bx = blockIdx.x;                     // win*16 + h
    const int tid = threadIdx.x;                   // query index t
    const size_t base = (size_t)bx * TT * HD;

    for (int idx = tid; idx < TT * HD; idx += 256) {
        sK[idx] = g_K[base + idx];
        sV[idx] = g_V[base + idx];
    }

    float q[HD];
    {
        const float4* qp = reinterpret_cast<const float4*>(g_Q + base + (size_t)tid * HD);
#pragma unroll
        for (int d4 = 0; d4 < 16; ++d4) {
            float4 v = qp[d4];
            q[4*d4+0]=v.x; q[4*d4+1]=v.y; q[4*d4+2]=v.z; q[4*d4+3]=v.w;
        }
    }
    __syncthreads();

    float mrun = -1e30f, l = 0.0f;
    float acc[HD];
#pragma unroll
    for (int d = 0; d < HD; ++d) acc[d] = 0.0f;

    for (int j = 0; j < TT; ++j) {
        const float4* k4 = reinterpret_cast<const float4*>(sK + j * HD);
        float s = 0.0f;
#pragma unroll
        for (int d4 = 0; d4 < 16; ++d4) {
            float4 kv = k4[d4];
            s += q[4*d4+0]*kv.x + q[4*d4+1]*kv.y + q[4*d4+2]*kv.z + q[4*d4+3]*kv.w;
        }
        const float4* v4 = reinterpret_cast<const float4*>(sV + j * HD);
        if (s <= mrun) {
            float p = __expf(s - mrun);
            l += p;
#pragma unroll
            for (int d4 = 0; d4 < 16; ++d4) {
                float4 vv = v4[d4];
                acc[4*d4+0] += p*vv.x; acc[4*d4+1] += p*vv.y;
                acc[4*d4+2] += p*vv.z; acc[4*d4+3] += p*vv.w;
            }
        } else {
            float corr = __expf(mrun - s);
            mrun = s;
            l = l * corr + 1.0f;
#pragma unroll
            for (int d4 = 0; d4 < 16; ++d4) {
                float4 vv = v4[d4];
                acc[4*d4+0] = acc[4*d4+0]*corr + vv.x;
                acc[4*d4+1] = acc[4*d4+1]*corr + vv.y;
                acc[4*d4+2] = acc[4*d4+2]*corr + vv.z;
                acc[4*d4+3] = acc[4*d4+3]*corr + vv.w;
            }
        }
    }

    const float inv = 1.0f / l;
    const int win = bx >> 4, h = bx & 15;
    const size_t orow = (size_t)(win * TT + tid) * CD + h * HD;
#pragma unroll
    for (int d8 = 0; d8 < 8; ++d8) {
        float v[8];
#pragma unroll
        for (int j = 0; j < 8; ++j) v[j] = acc[d8 * 8 + j] * inv;
        U4BF8 hi, lo; split8(v, hi, lo);
        reinterpret_cast<uint4*>(g_oh + orow + d8 * 8)[0] = hi.u;
        reinterpret_cast<uint4*>(g_ol + orow + d8 * 8)[0] = lo.u;
    }
}

// ---------------- launch ----------------
extern "C" void kernel_launch(void* const* d_in, const int* in_sizes, int n_in,
                              void* d_out, int out_size) {
    const float* x     = (const float*)d_in[0];
    // d_in[1] = position_ids (unused: window-local RoPE positions are fixed)
    const float* Wqkv  = (const float*)d_in[2];
    const float* Wproj = (const float*)d_in[3];
    float* out = (float*)d_out;

    const int attn_smem = 2 * TT * HD * (int)sizeof(float);   // 128 KB
    cudaFuncSetAttribute(attn_kernel, cudaFuncAttributeMaxDynamicSharedMemorySize, attn_smem);
    cudaFuncSetAttribute(hmma_gemm_kernel, cudaFuncAttributeMaxDynamicSharedMemorySize, GEMM_SMEM);

    init_tables_kernel<<<MTOT / 256, 256>>>();
    conv_x_kernel<<<(MTOT * (CD / 8)) / 256, 256>>>(x);
    conv_w_kernel<<<(C3 * CD / 8) / 256, 256>>>(Wqkv, 0);
    conv_w_kernel<<<(CD * CD / 8) / 256, 256>>>(Wproj, 1);

    dim3 g1(C3 / BN, MTOT / BM);   // 24 x 512
    hmma_gemm_kernel<<<g1, 256, GEMM_SMEM>>>(0, nullptr);

    attn_kernel<<<NWIN * NH, 256, attn_smem>>>();

    dim3 g2(CD / BN, MTOT / BM);   // 8 x 512
    hmma_gemm_kernel<<<g2, 256, GEMM_SMEM>>>(1, out);
}